// round 11
// baseline (speedup 1.0000x reference)
#include <cuda_runtime.h>

// CausalRevIN: B=16, T=8192, C=128, fp32.
// r8 lookback structure, but 256-thread CTAs with thread = 2 channels (float2):
// tile = 128 t (4 strips x 32 t), 1024 tiles, 8192 warps total for latency cover.

#define BB 16
#define TT 8192
#define TILE_T 128
#define SPW 32                  // timesteps per strip
#define SPB 64                  // tiles per series
#define NTILE (BB * SPB)        // 1024

#define STD_MIN 1e-5f
#define MAX_VAL 100.0f

__device__ float4 g_aggA_nm[NTILE * 32];
__device__ float4 g_aggA_x [NTILE * 32];
__device__ float4 g_incA_nm[NTILE * 32];
__device__ float4 g_incA_x [NTILE * 32];
__device__ float4 g_aggC   [NTILE * 32];
__device__ float4 g_incC   [NTILE * 32];
__device__ int    g_stateA [NTILE];
__device__ int    g_stateC [NTILE];
__device__ int    g_ticket;

__global__ void k_init() {
    int i = blockIdx.x * blockDim.x + threadIdx.x;
    if (i < NTILE) { g_stateA[i] = 0; g_stateC[i] = 0; }
    if (i == 0) g_ticket = 0;
}

__device__ __forceinline__ void f4add(float4& a, const float4 b) {
    a.x += b.x; a.y += b.y; a.z += b.z; a.w += b.w;
}
__device__ __forceinline__ void f2add(float2& a, const float2 b) {
    a.x += b.x; a.y += b.y;
}

__global__ void __launch_bounds__(256, 5) k_main(const float* __restrict__ x,
                                                 const float* __restrict__ m,
                                                 float* __restrict__ out) {
    __shared__ float2 s_a[256];
    __shared__ float2 s_b[256];
    __shared__ float2 e_n[64], e_x[64], e_s[64];
    __shared__ int sh_tile;

    const int tid = threadIdx.x;
    if (tid == 0) sh_tile = atomicAdd(&g_ticket, 1);
    __syncthreads();
    const int tile = sh_tile;
    const int b    = tile >> 6;
    const int seg  = tile & (SPB - 1);
    const int wh   = tid >> 6;          // strip 0..3 (32 t each)
    const int c2   = tid & 63;          // channel pair 0..63
    const int l    = tid & 31;          // lane (for warp 0 lookback)
    const int bbase = b << 6;

    const float2* __restrict__ x2 = (const float2*)x;
    const float2* __restrict__ m2 = (const float2*)m;
    float2* __restrict__ o2 = (float2*)out;
    // float2 index; row stride 64; max 8.39M fits int
    const int rowbase = (b * TT + seg * TILE_T + wh * SPW) * 64 + c2;

    // ================= Phase 1: load, pack mask bits, sum x =================
    float2 sx = make_float2(0.f, 0.f);
    unsigned nb0 = 0, nb1 = 0;
    #pragma unroll 8
    for (int t = 0; t < SPW; t++) {
        float2 xv = x2[rowbase + t * 64];
        float2 mv = __ldcs(&m2[rowbase + t * 64]);
        f2add(sx, xv);
        if (mv.x == 0.f) nb0 |= 1u << t;
        if (mv.y == 0.f) nb1 |= 1u << t;
    }
    float2 snm = make_float2((float)__popc(nb0), (float)__popc(nb1));
    s_a[tid] = snm; s_b[tid] = sx;
    __syncthreads();

    // exclusive prefix over strips (same channel pair)
    float2 we_n = make_float2(0.f, 0.f);
    float2 we_x = make_float2(0.f, 0.f);
    for (int ss = 0; ss < wh; ss++) { f2add(we_n, s_a[ss * 64 + c2]); f2add(we_x, s_b[ss * 64 + c2]); }

    // ================= Lookback A (warp 0, float4 over channel space) =================
    if (tid < 32) {
        float4 tot_nm = make_float4(0.f, 0.f, 0.f, 0.f);
        float4 tot_x  = make_float4(0.f, 0.f, 0.f, 0.f);
        #pragma unroll
        for (int ss = 0; ss < 4; ss++) {
            float2 u = s_a[ss * 64 + 2 * l], v = s_a[ss * 64 + 2 * l + 1];
            tot_nm.x += u.x; tot_nm.y += u.y; tot_nm.z += v.x; tot_nm.w += v.y;
            float2 p = s_b[ss * 64 + 2 * l], q = s_b[ss * 64 + 2 * l + 1];
            tot_x.x += p.x; tot_x.y += p.y; tot_x.z += q.x; tot_x.w += q.y;
        }
        float4 ex_nm = make_float4(0.f, 0.f, 0.f, 0.f);
        float4 ex_x  = make_float4(0.f, 0.f, 0.f, 0.f);
        if (seg != 0) {
            g_aggA_nm[tile * 32 + l] = tot_nm;
            g_aggA_x [tile * 32 + l] = tot_x;
            __threadfence();
            __syncwarp();
            if (l == 0) atomicExch(&g_stateA[tile], 1);

            int p_end = seg;
            for (;;) {
                int cnt = p_end < 32 ? p_end : 32;
                int s = 2;
                if (l < cnt) {
                    int pp = bbase + p_end - 1 - l;
                    do { s = atomicAdd(&g_stateA[pp], 0); } while (s == 0);
                }
                unsigned incmask = __ballot_sync(0xffffffffu, (s == 2) && (l < cnt));
                __threadfence();
                int li = incmask ? (__ffs(incmask) - 1) : -1;
                int nagg = (li >= 0) ? li : cnt;
                for (int j = 0; j < nagg; j++) {
                    int pidx = (bbase + p_end - 1 - j) * 32 + l;
                    f4add(ex_nm, __ldcg(&g_aggA_nm[pidx]));
                    f4add(ex_x,  __ldcg(&g_aggA_x [pidx]));
                }
                if (li >= 0) {
                    int pidx = (bbase + p_end - 1 - li) * 32 + l;
                    f4add(ex_nm, __ldcg(&g_incA_nm[pidx]));
                    f4add(ex_x,  __ldcg(&g_incA_x [pidx]));
                    break;
                }
                p_end -= cnt;
            }
        }
        float4 in_nm = ex_nm, in_x = ex_x;
        f4add(in_nm, tot_nm); f4add(in_x, tot_x);
        g_incA_nm[tile * 32 + l] = in_nm;
        g_incA_x [tile * 32 + l] = in_x;
        __threadfence();
        __syncwarp();
        if (l == 0) atomicExch(&g_stateA[tile], 2);
        e_n[2 * l]     = make_float2(ex_nm.x, ex_nm.y);
        e_n[2 * l + 1] = make_float2(ex_nm.z, ex_nm.w);
        e_x[2 * l]     = make_float2(ex_x.x, ex_x.y);
        e_x[2 * l + 1] = make_float2(ex_x.z, ex_x.w);
    }
    __syncthreads();
    float2 base_n = e_n[c2], base_x = e_x[c2];
    f2add(base_n, we_n); f2add(base_x, we_x);

    // ================= Phase 2: local sum of ((x-mean)*nm)^2 =================
    float2 cn = base_n, cx = base_x;
    float2 lss = make_float2(0.f, 0.f);
    #pragma unroll 8
    for (int t = 0; t < SPW; t++) {
        float2 xv = x2[rowbase + t * 64];
        #define STEP2(k, bits)                                            \
        {                                                                 \
            float nm = (bits & (1u << t)) ? 1.f : 0.f;                    \
            cn.k += nm; cx.k += xv.k;                                     \
            float n = fmaxf(cn.k, 1.f);                                   \
            float mean = cx.k * __fdividef(1.f, n);                       \
            float d = (xv.k - mean) * nm;                                 \
            lss.k += d * d;                                               \
        }
        STEP2(x, nb0) STEP2(y, nb1)
        #undef STEP2
    }
    s_a[tid] = lss;
    __syncthreads();
    float2 we_s = make_float2(0.f, 0.f);
    for (int ss = 0; ss < wh; ss++) f2add(we_s, s_a[ss * 64 + c2]);

    // ================= Lookback C (warp 0) =================
    if (tid < 32) {
        float4 tot_s = make_float4(0.f, 0.f, 0.f, 0.f);
        #pragma unroll
        for (int ss = 0; ss < 4; ss++) {
            float2 u = s_a[ss * 64 + 2 * l], v = s_a[ss * 64 + 2 * l + 1];
            tot_s.x += u.x; tot_s.y += u.y; tot_s.z += v.x; tot_s.w += v.y;
        }
        float4 ex_s = make_float4(0.f, 0.f, 0.f, 0.f);
        if (seg != 0) {
            g_aggC[tile * 32 + l] = tot_s;
            __threadfence();
            __syncwarp();
            if (l == 0) atomicExch(&g_stateC[tile], 1);

            int p_end = seg;
            for (;;) {
                int cnt = p_end < 32 ? p_end : 32;
                int s = 2;
                if (l < cnt) {
                    int pp = bbase + p_end - 1 - l;
                    do { s = atomicAdd(&g_stateC[pp], 0); } while (s == 0);
                }
                unsigned incmask = __ballot_sync(0xffffffffu, (s == 2) && (l < cnt));
                __threadfence();
                int li = incmask ? (__ffs(incmask) - 1) : -1;
                int nagg = (li >= 0) ? li : cnt;
                for (int j = 0; j < nagg; j++)
                    f4add(ex_s, __ldcg(&g_aggC[(bbase + p_end - 1 - j) * 32 + l]));
                if (li >= 0) {
                    f4add(ex_s, __ldcg(&g_incC[(bbase + p_end - 1 - li) * 32 + l]));
                    break;
                }
                p_end -= cnt;
            }
        }
        float4 in_s = ex_s; f4add(in_s, tot_s);
        g_incC[tile * 32 + l] = in_s;
        __threadfence();
        __syncwarp();
        if (l == 0) atomicExch(&g_stateC[tile], 2);
        e_s[2 * l]     = make_float2(ex_s.x, ex_s.y);
        e_s[2 * l + 1] = make_float2(ex_s.z, ex_s.w);
    }
    __syncthreads();
    float2 base_s = e_s[c2];
    f2add(base_s, we_s);

    // ================= Phase 3: normalize + clip, write out =================
    cn = base_n; cx = base_x;
    float2 cs = base_s;
    const float VMIN = STD_MIN * STD_MIN;
    #pragma unroll 8
    for (int t = 0; t < SPW; t++) {
        float2 xv = __ldcs(&x2[rowbase + t * 64]);
        float2 ov;
        #define STEP3(k, bits)                                            \
        {                                                                 \
            float nm = (bits & (1u << t)) ? 1.f : 0.f;                    \
            cn.k += nm; cx.k += xv.k;                                     \
            float n = fmaxf(cn.k, 1.f);                                   \
            float rn = __fdividef(1.f, n);                                \
            float mean = cx.k * rn;                                       \
            float num = xv.k - mean;                                      \
            float d = num * nm;                                           \
            cs.k += d * d;                                                \
            float var = cs.k * rn;                                        \
            float res = (var > VMIN) ? num * rsqrtf(var) : num;           \
            ov.k = fminf(fmaxf(res, -MAX_VAL), MAX_VAL);                  \
        }
        STEP3(x, nb0) STEP3(y, nb1)
        #undef STEP3
        __stcs(&o2[rowbase + t * 64], ov);
    }
}

extern "C" void kernel_launch(void* const* d_in, const int* in_sizes, int n_in,
                              void* d_out, int out_size) {
    const float* x = (const float*)d_in[0];
    const float* m = (const float*)d_in[1];
    float* out = (float*)d_out;

    k_init<<<(NTILE + 255) / 256, 256>>>();
    k_main<<<NTILE, 256>>>(x, m, out);
}